// round 7
// baseline (speedup 1.0000x reference)
#include <cuda_runtime.h>
#include <cuda_bf16.h>
#include <math.h>
#include <cstdint>

#define NN   100000
#define NE   1600000
#define HD   64
#define NG   256
#define NLAY 3
#define G3   192   // 3*HD

#define SCAN_TPB  512
#define SCAN_BLKS ((NN + SCAN_TPB - 1) / SCAN_TPB)   // 196

// ---------------- scratch (device globals; no allocation allowed) -------------
__device__ float g_h0[NN * HD];
__device__ float g_h1[NN * HD];
__device__ float g_agg[NN * HD];
__device__ int   g_rowptr[NN + 1];
__device__ int   g_cnt[NN];
__device__ int   g_aggv[SCAN_BLKS];
__device__ int   g_incv[SCAN_BLKS];
__device__ int   g_flag[SCAN_BLKS];
__device__ int   g_col[NE];
__device__ __nv_bfloat16 g_wfh[NLAY * G3 * HD];   // hi split of fused W@Wih^T, [l][gate][c]
__device__ __nv_bfloat16 g_wfl[NLAY * G3 * HD];   // lo split
__device__ __nv_bfloat16 g_whh_h[G3 * HD];
__device__ __nv_bfloat16 g_whh_l[G3 * HD];

// ---------------- ptx helpers (baseline ISA only: ldmatrix + mma.sync) --------
__device__ __forceinline__ uint32_t smem_u32(const void* p) {
    uint32_t a;
    asm("{ .reg .u64 t; cvta.to.shared.u64 t, %1; cvt.u32.u64 %0, t; }" : "=r"(a) : "l"(p));
    return a;
}
__device__ __forceinline__ void ldm4(uint32_t* r, uint32_t addr) {
    asm volatile("ldmatrix.sync.aligned.m8n8.x4.shared.b16 {%0,%1,%2,%3}, [%4];"
                 : "=r"(r[0]), "=r"(r[1]), "=r"(r[2]), "=r"(r[3]) : "r"(addr));
}
__device__ __forceinline__ void mma16816(float* d, const uint32_t* a, const uint32_t* b) {
    asm volatile(
        "mma.sync.aligned.m16n8k16.row.col.f32.bf16.bf16.f32 "
        "{%0,%1,%2,%3}, {%4,%5,%6,%7}, {%8,%9}, {%0,%1,%2,%3};"
        : "+f"(d[0]), "+f"(d[1]), "+f"(d[2]), "+f"(d[3])
        : "r"(a[0]), "r"(a[1]), "r"(a[2]), "r"(a[3]), "r"(b[0]), "r"(b[1]));
}
__device__ __forceinline__ uint32_t pack_bf16(float a, float b) {
    __nv_bfloat162 t = __floats2bfloat162_rn(a, b);
    return *(uint32_t*)&t;
}

// ---------------- prep: zero state + weight fusion + bf16 hi/lo split ---------
__global__ void prep_k(const float* __restrict__ W, const float* __restrict__ Wih,
                       const float* __restrict__ Whh, float* __restrict__ out) {
    int tid = blockIdx.x * blockDim.x + threadIdx.x;
    if (tid < NN) g_cnt[tid] = 0;
    if (tid < SCAN_BLKS) g_flag[tid] = 0;
    if (tid < NG * HD) out[tid] = 0.f;
    if (tid < NLAY * G3 * HD) {
        int c = tid & (HD - 1);
        int j = (tid >> 6) % G3;
        int l = tid / (G3 * HD);
        const float* wrow = W + (l * HD + c) * HD;
        const float* irow = Wih + j * HD;
        float s = 0.f;
#pragma unroll
        for (int k = 0; k < HD; k++) s = fmaf(wrow[k], irow[k], s);
        __nv_bfloat16 hi = __float2bfloat16(s);
        g_wfh[tid] = hi;
        g_wfl[tid] = __float2bfloat16(s - __bfloat162float(hi));
    }
    if (tid < G3 * HD) {
        float s = Whh[tid];
        __nv_bfloat16 hi = __float2bfloat16(s);
        g_whh_h[tid] = hi;
        g_whh_l[tid] = __float2bfloat16(s - __bfloat162float(hi));
    }
}

// ---------------- CSR build ----------------------------------------------------
__global__ void hist_k(const int* __restrict__ dst) {
    int e = blockIdx.x * blockDim.x + threadIdx.x;
    if (e < NE) atomicAdd(&g_cnt[dst[e]], 1);
}

// single-pass decoupled-lookback scan (196 blocks, all resident)
__global__ void scan_k() {
    __shared__ int ss[SCAN_TPB];
    __shared__ int s_excl;
    int t = threadIdx.x, b = blockIdx.x;
    int i = b * SCAN_TPB + t;
    int orig = (i < NN) ? g_cnt[i] : 0;
    ss[t] = orig;
    __syncthreads();
#pragma unroll
    for (int off = 1; off < SCAN_TPB; off <<= 1) {
        int u = (t >= off) ? ss[t - off] : 0;
        __syncthreads();
        ss[t] += u;
        __syncthreads();
    }
    int incl = ss[t];
    int total = ss[SCAN_TPB - 1];

    if (t == 0) {
        if (b == 0) {
            *(volatile int*)&g_incv[0] = total;
            __threadfence();
            *(volatile int*)&g_flag[0] = 2;
            s_excl = 0;
        } else {
            *(volatile int*)&g_aggv[b] = total;
            __threadfence();
            *(volatile int*)&g_flag[b] = 1;
        }
    }
    if (b > 0 && t < 32) {
        int running = 0;
        for (int base = b - 1; base >= 0; base -= 32) {
            int idx = base - t;
            int f;
            do {
                f = (idx >= 0) ? *(volatile int*)&g_flag[idx] : 2;
            } while (__any_sync(0xffffffffu, f == 0));
            __threadfence();
            int val = 0;
            if (idx >= 0)
                val = (f == 2) ? *(volatile int*)&g_incv[idx] : *(volatile int*)&g_aggv[idx];
            unsigned m = __ballot_sync(0xffffffffu, (f == 2) && idx >= 0);
            int firstP = m ? (__ffs(m) - 1) : 32;
            int contrib = (t <= firstP && idx >= 0) ? val : 0;
#pragma unroll
            for (int o = 16; o; o >>= 1) contrib += __shfl_down_sync(0xffffffffu, contrib, o);
            contrib = __shfl_sync(0xffffffffu, contrib, 0);
            running += contrib;
            if (m) break;
        }
        if (t == 0) {
            *(volatile int*)&g_incv[b] = running + total;
            __threadfence();
            *(volatile int*)&g_flag[b] = 2;
            s_excl = running;
        }
    }
    __syncthreads();
    int excl = s_excl + incl - orig;
    if (i < NN) {
        g_rowptr[i] = excl;
        g_cnt[i] = excl;   // scatter cursor
    }
    if (i == 0) g_rowptr[NN] = NE;
}

__global__ void scatter_k(const int* __restrict__ src, const int* __restrict__ dst) {
    int e = blockIdx.x * blockDim.x + threadIdx.x;
    if (e < NE) {
        int p = atomicAdd(&g_cnt[dst[e]], 1);
        g_col[p] = src[e];
    }
}

// ---------------- aggregation: one warp per node, float2 per lane --------------
__global__ void agg_k(const float2* __restrict__ h2, float2* __restrict__ out2) {
    int w    = (blockIdx.x * blockDim.x + threadIdx.x) >> 5;
    int lane = threadIdx.x & 31;
    if (w >= NN) return;
    int beg = g_rowptr[w], end = g_rowptr[w + 1];
    float2 acc = make_float2(0.f, 0.f);
    for (int base = beg; base < end; base += 32) {
        int m = min(32, end - base);
        int idx = 0;
        if (lane < m) idx = g_col[base + lane];
#pragma unroll 4
        for (int jj = 0; jj < m; jj++) {
            int s = __shfl_sync(0xffffffffu, idx, jj);
            float2 v = h2[s * 32 + lane];
            acc.x += v.x;
            acc.y += v.y;
        }
    }
    out2[w * 32 + lane] = acc;
}

// ---------------- GRU via mma.sync bf16 split: persistent blocks ---------------
// SMEM: A/H tiles (36864B) + weights (110592B, staged ONCE) + epilogue (67072B)
#define ROWB 144
#define OFF_AH 0
#define OFF_AL 9216
#define OFF_HH 18432
#define OFF_HL 27648
#define OFF_FH 36864
#define OFF_FL 64512
#define OFF_GH 92160
#define OFF_GL 119808
#define OFF_EPI 147456
#define GRU_SMEM 214528
#define NTILES ((NN + 63) / 64)   // 1563
#define GRU_GRID 148
#define GRU_TPB 384

__global__ void __launch_bounds__(GRU_TPB, 1) gru_mma(
    const float* __restrict__ agg, const float* __restrict__ hin,
    float* __restrict__ hout,
    const __nv_bfloat16* __restrict__ wfh, const __nv_bfloat16* __restrict__ wfl,
    const float* __restrict__ bih, const float* __restrict__ bhh) {
    extern __shared__ __align__(16) char sm[];
    int tid = threadIdx.x, wid = tid >> 5, lane = tid & 31;

    // ---- stage weights ONCE (bf16, [gate][c] rows) ----
    for (int i = tid; i < G3 * 16; i += GRU_TPB) {
        int r = i >> 4, c8 = i & 15;
        uint32_t off = r * ROWB + c8 * 8;
        *(uint2*)(sm + OFF_FH + off) = *(const uint2*)(wfh + r * 64 + c8 * 4);
        *(uint2*)(sm + OFF_FL + off) = *(const uint2*)(wfl + r * 64 + c8 * 4);
        *(uint2*)(sm + OFF_GH + off) = *(const uint2*)(g_whh_h + r * 64 + c8 * 4);
        *(uint2*)(sm + OFF_GL + off) = *(const uint2*)(g_whh_l + r * 64 + c8 * 4);
    }

    uint32_t sbase = smem_u32(sm);
    int mrow0 = (wid & 3) * 16;
    int n0g = (wid >> 2) * 64;
    uint32_t aOff = (mrow0 + (lane & 15)) * ROWB + ((lane >> 4) * 8) * 2;
    uint32_t bOff = (n0g + (lane >> 4) * 8 + (lane & 7)) * ROWB + (((lane >> 3) & 1) * 8) * 2;

    float* sRZ = (float*)(sm + OFF_EPI);           // [64][130]
    float* sIN = (float*)(sm + OFF_EPI + 33280);   // [64][66]
    float* sHN = (float*)(sm + OFF_EPI + 50176);   // [64][66]

    for (int tile = blockIdx.x; tile < NTILES; tile += GRU_GRID) {
        int n0 = tile * 64;
        __syncthreads();   // protect A/H + epi regions from previous iteration

        // ---- stage A/H (fp32 -> bf16 hi/lo) ----
        for (int i = tid; i < 64 * 16; i += GRU_TPB) {
            int t = i >> 4, c4 = i & 15;
            float4 a = make_float4(0.f, 0.f, 0.f, 0.f), h = a;
            if (n0 + t < NN) {
                a = ((const float4*)(agg + (size_t)(n0 + t) * HD))[c4];
                h = ((const float4*)(hin + (size_t)(n0 + t) * HD))[c4];
            }
            float av[4] = {a.x, a.y, a.z, a.w}, hv[4] = {h.x, h.y, h.z, h.w};
            float al[4], hl[4];
#pragma unroll
            for (int u = 0; u < 4; u++) {
                float th = __bfloat162float(__float2bfloat16(av[u]));
                al[u] = av[u] - th; av[u] = th;
                float t2 = __bfloat162float(__float2bfloat16(hv[u]));
                hl[u] = hv[u] - t2; hv[u] = t2;
            }
            uint32_t off = t * ROWB + c4 * 8;
            *(uint2*)(sm + OFF_AH + off) = make_uint2(pack_bf16(av[0], av[1]), pack_bf16(av[2], av[3]));
            *(uint2*)(sm + OFF_AL + off) = make_uint2(pack_bf16(al[0], al[1]), pack_bf16(al[2], al[3]));
            *(uint2*)(sm + OFF_HH + off) = make_uint2(pack_bf16(hv[0], hv[1]), pack_bf16(hv[2], hv[3]));
            *(uint2*)(sm + OFF_HL + off) = make_uint2(pack_bf16(hl[0], hl[1]), pack_bf16(hl[2], hl[3]));
        }
        __syncthreads();

        // ---- GEMMs, restructured to reuse A and B fragments ----
        // gi = AH*FH + AL*FH + AH*FL ; gh = HH*GH + HL*GH + HH*GL
        float dgi[32], dgh[32];
#pragma unroll
        for (int q = 0; q < 32; q++) { dgi[q] = 0.f; dgh[q] = 0.f; }

#pragma unroll
        for (int ks = 0; ks < 4; ks++) {
            uint32_t kb = ks * 32;
            uint32_t aH[4], aL[4], hH[4], hL[4];
            ldm4(aH, sbase + OFF_AH + aOff + kb);
            ldm4(aL, sbase + OFF_AL + aOff + kb);
            ldm4(hH, sbase + OFF_HH + aOff + kb);
            ldm4(hL, sbase + OFF_HL + aOff + kb);
#pragma unroll
            for (int np = 0; np < 4; np++) {
                uint32_t bo = bOff + np * 16 * ROWB + kb;
                uint32_t bFH[4], bGH[4];
                ldm4(bFH, sbase + OFF_FH + bo);
                ldm4(bGH, sbase + OFF_GH + bo);
                // p=0: AH*FH, p=1: AL*FH  (B fragment reused)
                mma16816(dgi + np * 8,     aH, bFH);
                mma16816(dgi + np * 8 + 4, aH, bFH + 2);
                mma16816(dgi + np * 8,     aL, bFH);
                mma16816(dgi + np * 8 + 4, aL, bFH + 2);
                mma16816(dgh + np * 8,     hH, bGH);
                mma16816(dgh + np * 8 + 4, hH, bGH + 2);
                mma16816(dgh + np * 8,     hL, bGH);
                mma16816(dgh + np * 8 + 4, hL, bGH + 2);
                // p=2: AH*FL / HH*GL  (A fragment reused)
                uint32_t bFL[4], bGL[4];
                ldm4(bFL, sbase + OFF_FL + bo);
                ldm4(bGL, sbase + OFF_GL + bo);
                mma16816(dgi + np * 8,     aH, bFL);
                mma16816(dgi + np * 8 + 4, aH, bFL + 2);
                mma16816(dgh + np * 8,     hH, bGL);
                mma16816(dgh + np * 8 + 4, hH, bGL + 2);
            }
        }

        // ---- distribute fragments to epilogue buffers ----
        int erow = lane >> 2;
        int ecol = (lane & 3) * 2;
#pragma unroll
        for (int nt = 0; nt < 8; nt++) {
            int g = n0g + nt * 8 + ecol;
#pragma unroll
            for (int hf = 0; hf < 2; hf++) {
                int row = mrow0 + erow + hf * 8;
                float gi0 = dgi[nt * 4 + hf * 2], gi1 = dgi[nt * 4 + hf * 2 + 1];
                float gh0 = dgh[nt * 4 + hf * 2], gh1 = dgh[nt * 4 + hf * 2 + 1];
                if (g < 128) {
                    *(float2*)(sRZ + row * 130 + g) = make_float2(gi0 + gh0, gi1 + gh1);
                } else {
                    *(float2*)(sIN + row * 66 + g - 128) = make_float2(gi0, gi1);
                    *(float2*)(sHN + row * 66 + g - 128) = make_float2(gh0, gh1);
                }
            }
        }
        __syncthreads();

        // ---- elementwise GRU + store ----
        for (int i = tid; i < 64 * 64; i += GRU_TPB) {
            int t = i >> 6, d = i & 63;
            if (n0 + t >= NN) continue;
            float ar = sRZ[t * 130 + d] + __ldg(bih + d) + __ldg(bhh + d);
            float az = sRZ[t * 130 + 64 + d] + __ldg(bih + 64 + d) + __ldg(bhh + 64 + d);
            float r = 1.f / (1.f + __expf(-ar));
            float z = 1.f / (1.f + __expf(-az));
            float xarg = sIN[t * 66 + d] + __ldg(bih + 128 + d) +
                         r * (sHN[t * 66 + d] + __ldg(bhh + 128 + d));
            float nn = 1.f - 2.f / (__expf(2.f * xarg) + 1.f);  // tanh
            float hp = hin[(size_t)(n0 + t) * HD + d];
            hout[(size_t)(n0 + t) * HD + d] = (1.f - z) * nn + z * hp;
        }
    }
}

// ---------------- pooling: batch sorted -> run-length accumulate ---------------
__global__ void pool_k(const float* __restrict__ h, const int* __restrict__ batch,
                       float* __restrict__ out) {
    int d = threadIdx.x;
    int n0 = blockIdx.x * 128;
    int nend = min(n0 + 128, NN);
    if (n0 >= NN) return;
    float acc = 0.f;
    int cur = batch[n0];
    for (int n = n0; n < nend; n++) {
        int b = batch[n];
        if (b != cur) {
            atomicAdd(&out[cur * HD + d], acc);
            acc = 0.f;
            cur = b;
        }
        acc += h[(size_t)n * HD + d];
    }
    atomicAdd(&out[cur * HD + d], acc);
}

// ---------------- launch --------------------------------------------------------
extern "C" void kernel_launch(void* const* d_in, const int* in_sizes, int n_in,
                              void* d_out, int out_size) {
    const float* x    = (const float*)d_in[0];
    const int*   ei   = (const int*)d_in[1];
    const int*   batch= (const int*)d_in[2];
    const float* W    = (const float*)d_in[3];
    const float* Wih  = (const float*)d_in[4];
    const float* Whh  = (const float*)d_in[5];
    const float* bih  = (const float*)d_in[6];
    const float* bhh  = (const float*)d_in[7];
    float* out = (float*)d_out;
    const int* src = ei;
    const int* dst = ei + NE;

    void *h0p, *h1p, *aggp, *wfhp, *wflp;
    cudaGetSymbolAddress(&h0p, g_h0);
    cudaGetSymbolAddress(&h1p, g_h1);
    cudaGetSymbolAddress(&aggp, g_agg);
    cudaGetSymbolAddress(&wfhp, g_wfh);
    cudaGetSymbolAddress(&wflp, g_wfl);

    cudaFuncSetAttribute(gru_mma, cudaFuncAttributeMaxDynamicSharedMemorySize, GRU_SMEM);

    prep_k<<<(NN + 255) / 256, 256>>>(W, Wih, Whh, out);          // launch 1
    hist_k<<<(NE + 255) / 256, 256>>>(dst);                        // launch 2
    scan_k<<<SCAN_BLKS, SCAN_TPB>>>();                             // launch 3
    scatter_k<<<(NE + 255) / 256, 256>>>(src, dst);                // launch 4

    const float* hin = x;
    for (int l = 0; l < NLAY; l++) {
        float* hout = (l & 1) ? (float*)h0p : (float*)h1p;
        agg_k<<<(NN * 32) / 256, 256>>>((const float2*)hin, (float2*)aggp);   // 5,7,9
        gru_mma<<<GRU_GRID, GRU_TPB, GRU_SMEM>>>(                              // 6,8,10
            (const float*)aggp, hin, hout,
            (const __nv_bfloat16*)wfhp + (size_t)l * G3 * HD,
            (const __nv_bfloat16*)wflp + (size_t)l * G3 * HD,
            bih, bhh);
        hin = hout;
    }
    pool_k<<<(NN + 127) / 128, 64>>>(hin, batch, out);             // launch 11
}

// round 8
// speedup vs baseline: 1.2121x; 1.2121x over previous
#include <cuda_runtime.h>
#include <cuda_bf16.h>
#include <math.h>
#include <cstdint>

#define NN   100000
#define NE   1600000
#define HD   64
#define NG   256
#define NLAY 3
#define G3   192   // 3*HD

#define SCAN_TPB  512
#define SCAN_BLKS ((NN + SCAN_TPB - 1) / SCAN_TPB)   // 196

// ---------------- scratch (device globals; no allocation allowed) -------------
__device__ float g_h0[NN * HD];
__device__ float g_h1[NN * HD];
__device__ float g_agg[NN * HD];
__device__ int   g_rowptr[NN + 1];
__device__ int   g_cnt[NN];
__device__ int   g_aggv[SCAN_BLKS];
__device__ int   g_incv[SCAN_BLKS];
__device__ int   g_flag[SCAN_BLKS];
__device__ int   g_col[NE];
__device__ __nv_bfloat16 g_wfh[NLAY * G3 * HD];   // hi split of fused W@Wih^T, [l][gate][c]
__device__ __nv_bfloat16 g_wfl[NLAY * G3 * HD];   // lo split
__device__ __nv_bfloat16 g_whh_h[G3 * HD];
__device__ __nv_bfloat16 g_whh_l[G3 * HD];

// ---------------- ptx helpers (baseline ISA only: ldmatrix + mma.sync) --------
__device__ __forceinline__ uint32_t smem_u32(const void* p) {
    uint32_t a;
    asm("{ .reg .u64 t; cvta.to.shared.u64 t, %1; cvt.u32.u64 %0, t; }" : "=r"(a) : "l"(p));
    return a;
}
__device__ __forceinline__ void ldm4(uint32_t* r, uint32_t addr) {
    asm volatile("ldmatrix.sync.aligned.m8n8.x4.shared.b16 {%0,%1,%2,%3}, [%4];"
                 : "=r"(r[0]), "=r"(r[1]), "=r"(r[2]), "=r"(r[3]) : "r"(addr));
}
__device__ __forceinline__ void mma16816(float* d, const uint32_t* a, const uint32_t* b) {
    asm volatile(
        "mma.sync.aligned.m16n8k16.row.col.f32.bf16.bf16.f32 "
        "{%0,%1,%2,%3}, {%4,%5,%6,%7}, {%8,%9}, {%0,%1,%2,%3};"
        : "+f"(d[0]), "+f"(d[1]), "+f"(d[2]), "+f"(d[3])
        : "r"(a[0]), "r"(a[1]), "r"(a[2]), "r"(a[3]), "r"(b[0]), "r"(b[1]));
}
__device__ __forceinline__ uint32_t pack_bf16(float a, float b) {
    __nv_bfloat162 t = __floats2bfloat162_rn(a, b);
    return *(uint32_t*)&t;
}

// ---------------- prep: zero state + weight fusion + bf16 hi/lo split ---------
__global__ void prep_k(const float* __restrict__ W, const float* __restrict__ Wih,
                       const float* __restrict__ Whh, float* __restrict__ out) {
    int tid = blockIdx.x * blockDim.x + threadIdx.x;
    if (tid < NN) g_cnt[tid] = 0;
    if (tid < SCAN_BLKS) g_flag[tid] = 0;
    if (tid < NG * HD) out[tid] = 0.f;
    if (tid < NLAY * G3 * HD) {
        int c = tid & (HD - 1);
        int j = (tid >> 6) % G3;
        int l = tid / (G3 * HD);
        const float* wrow = W + (l * HD + c) * HD;
        const float* irow = Wih + j * HD;
        float s = 0.f;
#pragma unroll
        for (int k = 0; k < HD; k++) s = fmaf(wrow[k], irow[k], s);
        __nv_bfloat16 hi = __float2bfloat16(s);
        g_wfh[tid] = hi;
        g_wfl[tid] = __float2bfloat16(s - __bfloat162float(hi));
    }
    if (tid < G3 * HD) {
        float s = Whh[tid];
        __nv_bfloat16 hi = __float2bfloat16(s);
        g_whh_h[tid] = hi;
        g_whh_l[tid] = __float2bfloat16(s - __bfloat162float(hi));
    }
}

// ---------------- CSR build ----------------------------------------------------
__global__ void hist_k(const int* __restrict__ dst) {
    int e = blockIdx.x * blockDim.x + threadIdx.x;
    if (e < NE) atomicAdd(&g_cnt[dst[e]], 1);
}

// single-pass decoupled-lookback scan (196 blocks, all resident)
__global__ void scan_k() {
    __shared__ int ss[SCAN_TPB];
    __shared__ int s_excl;
    int t = threadIdx.x, b = blockIdx.x;
    int i = b * SCAN_TPB + t;
    int orig = (i < NN) ? g_cnt[i] : 0;
    ss[t] = orig;
    __syncthreads();
#pragma unroll
    for (int off = 1; off < SCAN_TPB; off <<= 1) {
        int u = (t >= off) ? ss[t - off] : 0;
        __syncthreads();
        ss[t] += u;
        __syncthreads();
    }
    int incl = ss[t];
    int total = ss[SCAN_TPB - 1];

    if (t == 0) {
        if (b == 0) {
            *(volatile int*)&g_incv[0] = total;
            __threadfence();
            *(volatile int*)&g_flag[0] = 2;
            s_excl = 0;
        } else {
            *(volatile int*)&g_aggv[b] = total;
            __threadfence();
            *(volatile int*)&g_flag[b] = 1;
        }
    }
    if (b > 0 && t < 32) {
        int running = 0;
        for (int base = b - 1; base >= 0; base -= 32) {
            int idx = base - t;
            int f;
            do {
                f = (idx >= 0) ? *(volatile int*)&g_flag[idx] : 2;
            } while (__any_sync(0xffffffffu, f == 0));
            __threadfence();
            int val = 0;
            if (idx >= 0)
                val = (f == 2) ? *(volatile int*)&g_incv[idx] : *(volatile int*)&g_aggv[idx];
            unsigned m = __ballot_sync(0xffffffffu, (f == 2) && idx >= 0);
            int firstP = m ? (__ffs(m) - 1) : 32;
            int contrib = (t <= firstP && idx >= 0) ? val : 0;
#pragma unroll
            for (int o = 16; o; o >>= 1) contrib += __shfl_down_sync(0xffffffffu, contrib, o);
            contrib = __shfl_sync(0xffffffffu, contrib, 0);
            running += contrib;
            if (m) break;
        }
        if (t == 0) {
            *(volatile int*)&g_incv[b] = running + total;
            __threadfence();
            *(volatile int*)&g_flag[b] = 2;
            s_excl = running;
        }
    }
    __syncthreads();
    int excl = s_excl + incl - orig;
    if (i < NN) {
        g_rowptr[i] = excl;
        g_cnt[i] = excl;   // scatter cursor
    }
    if (i == 0) g_rowptr[NN] = NE;
}

__global__ void scatter_k(const int* __restrict__ src, const int* __restrict__ dst) {
    int e = blockIdx.x * blockDim.x + threadIdx.x;
    if (e < NE) {
        int p = atomicAdd(&g_cnt[dst[e]], 1);
        g_col[p] = src[e];
    }
}

// ---------------- aggregation: one warp per node, float2 per lane --------------
__global__ void agg_k(const float2* __restrict__ h2, float2* __restrict__ out2) {
    int w    = (blockIdx.x * blockDim.x + threadIdx.x) >> 5;
    int lane = threadIdx.x & 31;
    if (w >= NN) return;
    int beg = g_rowptr[w], end = g_rowptr[w + 1];
    float2 acc = make_float2(0.f, 0.f);
    for (int base = beg; base < end; base += 32) {
        int m = min(32, end - base);
        int idx = 0;
        if (lane < m) idx = g_col[base + lane];
#pragma unroll 4
        for (int jj = 0; jj < m; jj++) {
            int s = __shfl_sync(0xffffffffu, idx, jj);
            float2 v = h2[s * 32 + lane];
            acc.x += v.x;
            acc.y += v.y;
        }
    }
    out2[w * 32 + lane] = acc;
}

// ---------------- GRU via mma.sync bf16 split: register epilogue ---------------
// Each warp owns a 16-row x 32-feature patch and computes ALL THREE gate planes
// (g = d, d+64, d+128) for it, so r/z/n land in the same thread's registers and
// the GRU nonlinearity needs no SMEM exchange at all.
#define ROWB 144
#define OFF_AH 0
#define OFF_AL 9216
#define OFF_HH 18432
#define OFF_HL 27648
#define OFF_FH 36864
#define OFF_FL 64512
#define OFF_GH 92160
#define OFF_GL 119808
#define GRU_SMEM 147456
#define NTILES ((NN + 63) / 64)   // 1563
#define GRU_GRID 148
#define GRU_TPB 256

#define IDX(p, t, h) ((((p) * 2 + (t)) * 2 + (h)) * 4)

__global__ void __launch_bounds__(GRU_TPB, 1) gru_mma(
    const float* __restrict__ agg, const float* __restrict__ hin,
    float* __restrict__ hout,
    const __nv_bfloat16* __restrict__ wfh, const __nv_bfloat16* __restrict__ wfl,
    const float* __restrict__ bih, const float* __restrict__ bhh) {
    extern __shared__ __align__(16) char sm[];
    int tid = threadIdx.x, wid = tid >> 5, lane = tid & 31;

    // ---- stage weights ONCE (bf16, [gate][c] rows) ----
    for (int i = tid; i < G3 * 16; i += GRU_TPB) {
        int r = i >> 4, c8 = i & 15;
        uint32_t off = r * ROWB + c8 * 8;
        *(uint2*)(sm + OFF_FH + off) = *(const uint2*)(wfh + r * 64 + c8 * 4);
        *(uint2*)(sm + OFF_FL + off) = *(const uint2*)(wfl + r * 64 + c8 * 4);
        *(uint2*)(sm + OFF_GH + off) = *(const uint2*)(g_whh_h + r * 64 + c8 * 4);
        *(uint2*)(sm + OFF_GL + off) = *(const uint2*)(g_whh_l + r * 64 + c8 * 4);
    }

    uint32_t sbase = smem_u32(sm);
    int mrow0 = (wid & 3) * 16;        // 4 M-stripes of 16 rows
    int d0 = (wid >> 2) * 32;          // 2 feature groups of 32
    uint32_t aOff = (mrow0 + (lane & 15)) * ROWB + (lane >> 4) * 16;
    uint32_t bRow = (lane >> 4) * 8 + (lane & 7);
    uint32_t bCol = ((lane >> 3) & 1) * 16;

    // per-thread bias preload: d = d0 + t*16 + h*8 + (lane&3)*2 + j, m=(t*2+h)*2+j
    float brz[8], bz[8], bin_[8], bhn[8];
#pragma unroll
    for (int t = 0; t < 2; t++)
#pragma unroll
        for (int h = 0; h < 2; h++)
#pragma unroll
            for (int j = 0; j < 2; j++) {
                int m = (t * 2 + h) * 2 + j;
                int d = d0 + t * 16 + h * 8 + (lane & 3) * 2 + j;
                brz[m]  = __ldg(bih + d) + __ldg(bhh + d);
                bz[m]   = __ldg(bih + 64 + d) + __ldg(bhh + 64 + d);
                bin_[m] = __ldg(bih + 128 + d);
                bhn[m]  = __ldg(bhh + 128 + d);
            }

    for (int tile = blockIdx.x; tile < NTILES; tile += GRU_GRID) {
        int n0 = tile * 64;
        __syncthreads();   // staging region reuse vs previous tile's readers

        // ---- stage A/H (fp32 -> bf16 hi/lo) ----
        for (int i = tid; i < 64 * 16; i += GRU_TPB) {
            int t = i >> 4, c4 = i & 15;
            float4 a = make_float4(0.f, 0.f, 0.f, 0.f), h = a;
            if (n0 + t < NN) {
                a = ((const float4*)(agg + (size_t)(n0 + t) * HD))[c4];
                h = ((const float4*)(hin + (size_t)(n0 + t) * HD))[c4];
            }
            float av[4] = {a.x, a.y, a.z, a.w}, hv[4] = {h.x, h.y, h.z, h.w};
            float al[4], hl[4];
#pragma unroll
            for (int u = 0; u < 4; u++) {
                float th = __bfloat162float(__float2bfloat16(av[u]));
                al[u] = av[u] - th; av[u] = th;
                float t2 = __bfloat162float(__float2bfloat16(hv[u]));
                hl[u] = hv[u] - t2; hv[u] = t2;
            }
            uint32_t off = t * ROWB + c4 * 8;
            *(uint2*)(sm + OFF_AH + off) = make_uint2(pack_bf16(av[0], av[1]), pack_bf16(av[2], av[3]));
            *(uint2*)(sm + OFF_AL + off) = make_uint2(pack_bf16(al[0], al[1]), pack_bf16(al[2], al[3]));
            *(uint2*)(sm + OFF_HH + off) = make_uint2(pack_bf16(hv[0], hv[1]), pack_bf16(hv[2], hv[3]));
            *(uint2*)(sm + OFF_HL + off) = make_uint2(pack_bf16(hl[0], hl[1]), pack_bf16(hl[2], hl[3]));
        }
        __syncthreads();

        // ---- GEMMs: 3 gate planes x 2 n16 groups per warp ----
        float dgi[48], dgh[48];
#pragma unroll
        for (int q = 0; q < 48; q++) { dgi[q] = 0.f; dgh[q] = 0.f; }

#pragma unroll
        for (int ks = 0; ks < 4; ks++) {
            uint32_t kb = ks * 32;
            uint32_t aH[4], aL[4], hH[4], hL[4];
            ldm4(aH, sbase + OFF_AH + aOff + kb);
            ldm4(aL, sbase + OFF_AL + aOff + kb);
            ldm4(hH, sbase + OFF_HH + aOff + kb);
            ldm4(hL, sbase + OFF_HL + aOff + kb);
#pragma unroll
            for (int p = 0; p < 3; p++) {
#pragma unroll
                for (int t = 0; t < 2; t++) {
                    uint32_t bo = (p * 64 + d0 + t * 16 + bRow) * ROWB + bCol + kb;
                    int I = IDX(p, t, 0);
                    uint32_t bFH[4], bGH[4];
                    ldm4(bFH, sbase + OFF_FH + bo);
                    ldm4(bGH, sbase + OFF_GH + bo);
                    mma16816(dgi + I,     aH, bFH);
                    mma16816(dgi + I + 4, aH, bFH + 2);
                    mma16816(dgi + I,     aL, bFH);
                    mma16816(dgi + I + 4, aL, bFH + 2);
                    mma16816(dgh + I,     hH, bGH);
                    mma16816(dgh + I + 4, hH, bGH + 2);
                    mma16816(dgh + I,     hL, bGH);
                    mma16816(dgh + I + 4, hL, bGH + 2);
                    uint32_t bFL[4], bGL[4];
                    ldm4(bFL, sbase + OFF_FL + bo);
                    ldm4(bGL, sbase + OFF_GL + bo);
                    mma16816(dgi + I,     aH, bFL);
                    mma16816(dgi + I + 4, aH, bFL + 2);
                    mma16816(dgh + I,     hH, bGL);
                    mma16816(dgh + I + 4, hH, bGL + 2);
                }
            }
        }

        // ---- register epilogue: r/z/n are in this thread's accumulators ----
#pragma unroll
        for (int t = 0; t < 2; t++)
#pragma unroll
            for (int h = 0; h < 2; h++) {
                int dE = d0 + t * 16 + h * 8 + (lane & 3) * 2;
#pragma unroll
                for (int rh = 0; rh < 2; rh++) {
                    int row = mrow0 + (lane >> 2) + rh * 8;
                    if (n0 + row >= NN) continue;
                    uint32_t o = row * ROWB + dE * 2;
                    __nv_bfloat162 p2h = *(const __nv_bfloat162*)(sm + OFF_HH + o);
                    __nv_bfloat162 p2l = *(const __nv_bfloat162*)(sm + OFF_HL + o);
                    float hp[2] = {__bfloat162float(p2h.x) + __bfloat162float(p2l.x),
                                   __bfloat162float(p2h.y) + __bfloat162float(p2l.y)};
                    float outv[2];
#pragma unroll
                    for (int j = 0; j < 2; j++) {
                        int q = rh * 2 + j;
                        int m = (t * 2 + h) * 2 + j;
                        float ar = dgi[IDX(0, t, h) + q] + dgh[IDX(0, t, h) + q] + brz[m];
                        float az = dgi[IDX(1, t, h) + q] + dgh[IDX(1, t, h) + q] + bz[m];
                        float r = 1.f / (1.f + __expf(-ar));
                        float z = 1.f / (1.f + __expf(-az));
                        float xarg = dgi[IDX(2, t, h) + q] + bin_[m] +
                                     r * (dgh[IDX(2, t, h) + q] + bhn[m]);
                        float nn = 1.f - 2.f / (__expf(2.f * xarg) + 1.f);  // tanh
                        outv[j] = (1.f - z) * nn + z * hp[j];
                    }
                    *(float2*)(hout + (size_t)(n0 + row) * HD + dE) =
                        make_float2(outv[0], outv[1]);
                }
            }
    }
}

// ---------------- pooling: batch sorted -> run-length accumulate ---------------
__global__ void pool_k(const float* __restrict__ h, const int* __restrict__ batch,
                       float* __restrict__ out) {
    int d = threadIdx.x;
    int n0 = blockIdx.x * 128;
    int nend = min(n0 + 128, NN);
    if (n0 >= NN) return;
    float acc = 0.f;
    int cur = batch[n0];
    for (int n = n0; n < nend; n++) {
        int b = batch[n];
        if (b != cur) {
            atomicAdd(&out[cur * HD + d], acc);
            acc = 0.f;
            cur = b;
        }
        acc += h[(size_t)n * HD + d];
    }
    atomicAdd(&out[cur * HD + d], acc);
}

// ---------------- launch --------------------------------------------------------
extern "C" void kernel_launch(void* const* d_in, const int* in_sizes, int n_in,
                              void* d_out, int out_size) {
    const float* x    = (const float*)d_in[0];
    const int*   ei   = (const int*)d_in[1];
    const int*   batch= (const int*)d_in[2];
    const float* W    = (const float*)d_in[3];
    const float* Wih  = (const float*)d_in[4];
    const float* Whh  = (const float*)d_in[5];
    const float* bih  = (const float*)d_in[6];
    const float* bhh  = (const float*)d_in[7];
    float* out = (float*)d_out;
    const int* src = ei;
    const int* dst = ei + NE;

    void *h0p, *h1p, *aggp, *wfhp, *wflp;
    cudaGetSymbolAddress(&h0p, g_h0);
    cudaGetSymbolAddress(&h1p, g_h1);
    cudaGetSymbolAddress(&aggp, g_agg);
    cudaGetSymbolAddress(&wfhp, g_wfh);
    cudaGetSymbolAddress(&wflp, g_wfl);

    cudaFuncSetAttribute(gru_mma, cudaFuncAttributeMaxDynamicSharedMemorySize, GRU_SMEM);

    prep_k<<<(NN + 255) / 256, 256>>>(W, Wih, Whh, out);          // launch 1
    hist_k<<<(NE + 255) / 256, 256>>>(dst);                        // launch 2
    scan_k<<<SCAN_BLKS, SCAN_TPB>>>();                             // launch 3
    scatter_k<<<(NE + 255) / 256, 256>>>(src, dst);                // launch 4

    const float* hin = x;
    for (int l = 0; l < NLAY; l++) {
        float* hout = (l & 1) ? (float*)h0p : (float*)h1p;
        agg_k<<<(NN * 32) / 256, 256>>>((const float2*)hin, (float2*)aggp);   // 5,7,9
        gru_mma<<<GRU_GRID, GRU_TPB, GRU_SMEM>>>(                              // 6,8,10
            (const float*)aggp, hin, hout,
            (const __nv_bfloat16*)wfhp + (size_t)l * G3 * HD,
            (const __nv_bfloat16*)wflp + (size_t)l * G3 * HD,
            bih, bhh);
        hin = hout;
    }
    pool_k<<<(NN + 127) / 128, 64>>>(hin, batch, out);             // launch 11
}